// round 3
// baseline (speedup 1.0000x reference)
#include <cuda_runtime.h>

// LinearMPO: out[l, a*CHI+x, i, b*CHI+y] = sum_j cores[l,a,i,j,b] * mps[l,x,j,y]
// L=32, D=4, d=2, CHI=256.
// mps:   [32,256,2,256]  strides l:131072 x:512 j:256 y:1
// cores: [32,4,2,2,4]    strides l:64 a:16 i:8 j:4 b:1
// out:   [32,1024,2,1024] flat: ((l*1024 + a*256 + x)*2 + i)*1024 + b*256 + y

#define L_  32
#define D_  4
#define d_  2
#define CHI_ 256

__global__ __launch_bounds__(256)
void mpo_mps_kernel(const float* __restrict__ mps,
                    const float* __restrict__ cores,
                    float* __restrict__ out)
{
    // Each block handles 4 consecutive x at a fixed l.
    // 64 blocks per l, 32 l -> 2048 blocks.
    const int blk = blockIdx.x;
    const int l   = blk >> 6;            // / 64
    const int x0  = (blk & 63) << 2;     // *4
    const int tid = threadIdx.x;
    const int g   = tid >> 6;            // which x in this block (0..3)
    const int ty  = tid & 63;            // float4 group along y (0..63)
    const int x   = x0 + g;

    // Stage this site's 64 core coefficients in shared memory (broadcast reads).
    __shared__ float sc[64];
    if (tid < 64) sc[tid] = cores[l * 64 + tid];
    __syncthreads();

    // Load the two physical-index rows of the MPS for (l, x): 2 x 256 floats.
    const float4* m0p = reinterpret_cast<const float4*>(mps + ((size_t)(l * CHI_ + x) * d_ + 0) * CHI_);
    const float4* m1p = reinterpret_cast<const float4*>(mps + ((size_t)(l * CHI_ + x) * d_ + 1) * CHI_);
    const float4 m0 = m0p[ty];
    const float4 m1 = m1p[ty];

    // Base output offset for (l, x, y-group).
    const size_t lbase = (size_t)l * (D_ * CHI_ * d_ * D_ * CHI_)   // l * 2097152
                       + (size_t)x * (d_ * D_ * CHI_)               // x * 2048
                       + (size_t)ty * 4;

    #pragma unroll
    for (int a = 0; a < D_; ++a) {
        #pragma unroll
        for (int i = 0; i < d_; ++i) {
            #pragma unroll
            for (int b = 0; b < D_; ++b) {
                const float c0 = sc[a * 16 + i * 8 + 0 + b];   // j=0
                const float c1 = sc[a * 16 + i * 8 + 4 + b];   // j=1
                float4 r;
                r.x = fmaf(c0, m0.x, c1 * m1.x);
                r.y = fmaf(c0, m0.y, c1 * m1.y);
                r.z = fmaf(c0, m0.z, c1 * m1.z);
                r.w = fmaf(c0, m0.w, c1 * m1.w);
                const size_t off = lbase
                                 + (size_t)a * (CHI_ * d_ * D_ * CHI_)  // a * 524288
                                 + (size_t)i * (D_ * CHI_)              // i * 1024
                                 + (size_t)b * CHI_;                    // b * 256
                *reinterpret_cast<float4*>(out + off) = r;
            }
        }
    }
}

extern "C" void kernel_launch(void* const* d_in, const int* in_sizes, int n_in,
                              void* d_out, int out_size)
{
    const float* mps   = (const float*)d_in[0];
    const float* cores = (const float*)d_in[1];
    // Defensive: identify by element count (mps=4194304, cores=2048).
    if (n_in >= 2 && in_sizes[0] == 2048) {
        const float* t = mps; mps = cores; cores = t;
    }
    float* out = (float*)d_out;

    dim3 grid(2048);
    dim3 block(256);
    mpo_mps_kernel<<<grid, block>>>(mps, cores, out);
}

// round 4
// speedup vs baseline: 1.0148x; 1.0148x over previous
#include <cuda_runtime.h>

// LinearMPO: out[l, a*CHI+x, i, b*CHI+y] = sum_j cores[l,a,i,j,b] * mps[l,x,j,y]
// L=32, D=4, d=2, CHI=256.
// mps:   [32,256,2,256]  strides l:131072 x:512 j:256 y:1
// cores: [32,4,2,2,4]    strides l:64 a:16 i:8 j:4 b:1
// out:   [32,1024,2,1024] flat: ((l*1024 + a*256 + x)*2 + i)*1024 + b*256 + y
//
// R3: 50.6us, DRAM 59.7% (4.88 TB/s), L2 51%, issue 12.5% -> store backpressure.
// R4 change: streaming cache hints (__stcs on output, __ldcs on mps) to stop the
// 256MB output stream from thrashing L2 (zero reuse on either stream).

#define L_  32
#define D_  4
#define d_  2
#define CHI_ 256

__global__ __launch_bounds__(256)
void mpo_mps_kernel(const float* __restrict__ mps,
                    const float* __restrict__ cores,
                    float* __restrict__ out)
{
    // Each block handles 4 consecutive x at a fixed l.
    // 64 blocks per l, 32 l -> 2048 blocks.
    const int blk = blockIdx.x;
    const int l   = blk >> 6;            // / 64
    const int x0  = (blk & 63) << 2;     // *4
    const int tid = threadIdx.x;
    const int g   = tid >> 6;            // which x in this block (0..3)
    const int ty  = tid & 63;            // float4 group along y (0..63)
    const int x   = x0 + g;

    // Stage this site's 64 core coefficients in shared memory (broadcast reads).
    __shared__ float sc[64];
    if (tid < 64) sc[tid] = cores[l * 64 + tid];
    __syncthreads();

    // Load the two physical-index rows of the MPS for (l, x): 2 x 256 floats.
    // Streaming loads: each mps row is consumed by exactly 1 block -> no L2 reuse
    // worth preserving at the expense of the output stream.
    const float4* m0p = reinterpret_cast<const float4*>(mps + ((size_t)(l * CHI_ + x) * d_ + 0) * CHI_);
    const float4* m1p = reinterpret_cast<const float4*>(mps + ((size_t)(l * CHI_ + x) * d_ + 1) * CHI_);
    const float4 m0 = __ldcs(m0p + ty);
    const float4 m1 = __ldcs(m1p + ty);

    // Base output offset for (l, x, y-group).
    const size_t lbase = (size_t)l * (D_ * CHI_ * d_ * D_ * CHI_)   // l * 2097152
                       + (size_t)x * (d_ * D_ * CHI_)               // x * 2048
                       + (size_t)ty * 4;

    #pragma unroll
    for (int a = 0; a < D_; ++a) {
        #pragma unroll
        for (int i = 0; i < d_; ++i) {
            #pragma unroll
            for (int b = 0; b < D_; ++b) {
                const float c0 = sc[a * 16 + i * 8 + 0 + b];   // j=0
                const float c1 = sc[a * 16 + i * 8 + 4 + b];   // j=1
                float4 r;
                r.x = fmaf(c0, m0.x, c1 * m1.x);
                r.y = fmaf(c0, m0.y, c1 * m1.y);
                r.z = fmaf(c0, m0.z, c1 * m1.z);
                r.w = fmaf(c0, m0.w, c1 * m1.w);
                const size_t off = lbase
                                 + (size_t)a * (CHI_ * d_ * D_ * CHI_)  // a * 524288
                                 + (size_t)i * (D_ * CHI_)              // i * 1024
                                 + (size_t)b * CHI_;                    // b * 256
                // Streaming store: evict-first, don't let 256MB of write-once
                // data churn L2.
                __stcs(reinterpret_cast<float4*>(out + off), r);
            }
        }
    }
}

extern "C" void kernel_launch(void* const* d_in, const int* in_sizes, int n_in,
                              void* d_out, int out_size)
{
    const float* mps   = (const float*)d_in[0];
    const float* cores = (const float*)d_in[1];
    // Defensive: identify by element count (mps=4194304, cores=2048).
    if (n_in >= 2 && in_sizes[0] == 2048) {
        const float* t = mps; mps = cores; cores = t;
    }
    float* out = (float*)d_out;

    dim3 grid(2048);
    dim3 block(256);
    mpo_mps_kernel<<<grid, block>>>(mps, cores, out);
}